// round 3
// baseline (speedup 1.0000x reference)
#include <cuda_runtime.h>
#include <math.h>

#define NN   50000
#define EE   1600000
#define ETOT (EE+NN)
#define IND  64
#define HID  128
#define NH   4
#define HD   32
#define OUTD 64
#define EPS  1e-5f

// ---------------- scratch (device globals; no allocation allowed) ----------
__device__ __align__(16) float    g_h  [NN*HID];   // activations between stages
__device__ __align__(16) float    g_hW [NN*HID];   // h @ W per GAT layer
__device__ __align__(16) float    g_agg[NN*HID];   // GAT aggregation output
__device__ __align__(16) float4   g_es [NN];       // per-node per-head src score
__device__ __align__(16) float4   g_ed [NN];       // per-node per-head dst score
__device__ unsigned g_m  [NN*NH];                  // segment max (order-encoded)
__device__ float    g_den[NN*NH];                  // segment softmax denominator

// ---------------- helpers --------------------------------------------------
__device__ __forceinline__ float gelu_f(float x){
  return 0.5f*x*(1.f+tanhf(0.7978845608028654f*(x+0.044715f*x*x*x)));
}
__device__ __forceinline__ float lrelu(float x){ return x>0.f ? x : 0.2f*x; }
// order-preserving float->uint for atomicMax; encode of any finite float > 0,
// and 0 decodes to a huge negative, so zero-init is a safe -inf sentinel.
__device__ __forceinline__ unsigned f2o(float f){
  unsigned b=__float_as_uint(f);
  return (b&0x80000000u)? ~b : (b|0x80000000u);
}
__device__ __forceinline__ float o2f(unsigned u){
  return (u&0x80000000u)? __uint_as_float(u&0x7fffffffu) : __uint_as_float(~u);
}
__device__ __forceinline__ int clampN(int v){
  return v<0?0:(v>=NN?NN-1:v);
}

// ---------------- stage 1: h = gelu(LN(x @ w_in + b_in)) -------------------
// 128 threads, 16 rows/block. 2D register tile: 4 cols x 4 rows per thread.
__global__ void __launch_bounds__(128) k_in(
    const float* __restrict__ x, const float* __restrict__ w,
    const float* __restrict__ b, const float* __restrict__ gam,
    const float* __restrict__ bet)
{
  __shared__ float ws[IND*HID];   // 32 KB
  __shared__ float xs[16*IND];    //  4 KB
  __shared__ float hb[16*HID];    //  8 KB
  const int t = threadIdx.x;
  const int row0 = blockIdx.x*16;   // 50000/16 = 3125 exact

  for(int i=t;i<IND*HID;i+=128) ws[i]=w[i];
  for(int i=t;i<16*IND;i+=128)  xs[i]=x[row0*IND+i];
  __syncthreads();

  const int cg=t&31, rg=t>>5;       // cols 4*cg..4*cg+3, rows rg*4..rg*4+3
  float4 bb=*(const float4*)&b[4*cg];
  float acc[4][4];
  #pragma unroll
  for(int r=0;r<4;r++){acc[r][0]=bb.x;acc[r][1]=bb.y;acc[r][2]=bb.z;acc[r][3]=bb.w;}

  for(int k=0;k<IND;k++){
    float4 wv=*(float4*)&ws[k*HID+4*cg];
    #pragma unroll
    for(int r=0;r<4;r++){
      float hv=xs[(rg*4+r)*IND+k];
      acc[r][0]+=hv*wv.x; acc[r][1]+=hv*wv.y; acc[r][2]+=hv*wv.z; acc[r][3]+=hv*wv.w;
    }
  }
  #pragma unroll
  for(int r=0;r<4;r++)
    *(float4*)&hb[(rg*4+r)*HID+4*cg]=make_float4(acc[r][0],acc[r][1],acc[r][2],acc[r][3]);
  __syncthreads();

  // LN + gelu: warp per row (4 rows per warp)
  const int lane=t&31, wid=t>>5;
  float4 gg=*(const float4*)&gam[lane*4];
  float4 b2=*(const float4*)&bet[lane*4];
  for(int r=wid;r<16;r+=4){
    float4 v=*(float4*)&hb[r*HID+lane*4];
    float s=v.x+v.y+v.z+v.w;
    float q=v.x*v.x+v.y*v.y+v.z*v.z+v.w*v.w;
    #pragma unroll
    for(int o=16;o;o>>=1){
      s+=__shfl_xor_sync(0xffffffffu,s,o);
      q+=__shfl_xor_sync(0xffffffffu,q,o);
    }
    float mu=s*(1.f/HID);
    float rs=rsqrtf(q*(1.f/HID)-mu*mu+EPS);
    v.x=gelu_f((v.x-mu)*rs*gg.x+b2.x);
    v.y=gelu_f((v.y-mu)*rs*gg.y+b2.y);
    v.z=gelu_f((v.z-mu)*rs*gg.z+b2.z);
    v.w=gelu_f((v.w-mu)*rs*gg.w+b2.w);
    *(float4*)&g_h[(row0+r)*HID+lane*4]=v;
  }
}

// ---------------- stage 2: hW = h @ W ; e_src/e_dst ------------------------
// 128 threads, 32 rows/block, dynamic smem 96 KB.
__global__ void __launch_bounds__(128) k_hw(
    const float* __restrict__ W, const float* __restrict__ asrc,
    const float* __restrict__ adst)
{
  extern __shared__ float sm[];
  float* Ws  = sm;                 // 64 KB
  float* hs  = sm + HID*HID;       // 16 KB
  float* hwb = hs + 32*HID;        // 16 KB
  const int t = threadIdx.x;
  const int row0 = blockIdx.x*32;
  const int nrows = min(32, NN-row0);

  for(int i=t;i<HID*HID;i+=128) Ws[i]=W[i];
  for(int i=t;i<nrows*HID;i+=128) hs[i]=g_h[row0*HID+i];
  for(int i=nrows*HID+t;i<32*HID;i+=128) hs[i]=0.f;
  __syncthreads();

  const int cg=t&31, rg=t>>5;      // cols 4*cg.., rows rg*8..rg*8+7
  float acc[8][4];
  #pragma unroll
  for(int r=0;r<8;r++){acc[r][0]=0;acc[r][1]=0;acc[r][2]=0;acc[r][3]=0;}

  for(int k=0;k<HID;k++){
    float4 wv=*(float4*)&Ws[k*HID+4*cg];
    #pragma unroll
    for(int r=0;r<8;r++){
      float hv=hs[(rg*8+r)*HID+k];
      acc[r][0]+=hv*wv.x; acc[r][1]+=hv*wv.y; acc[r][2]+=hv*wv.z; acc[r][3]+=hv*wv.w;
    }
  }
  #pragma unroll
  for(int r=0;r<8;r++)
    *(float4*)&hwb[(rg*8+r)*HID+4*cg]=make_float4(acc[r][0],acc[r][1],acc[r][2],acc[r][3]);
  __syncthreads();

  for(int i=t;i<nrows*HID;i+=128) g_hW[row0*HID+i]=hwb[i];

  // attention scores: warp per row, 4 heads reduced with a warp butterfly
  const int lane=t&31, wid=t>>5;
  for(int r=wid;r<nrows;r+=4){
    float ps[NH], pd[NH];
    #pragma unroll
    for(int h=0;h<NH;h++){
      float v=hwb[r*HID+h*HD+lane];
      ps[h]=v*asrc[h*HD+lane];
      pd[h]=v*adst[h*HD+lane];
    }
    #pragma unroll
    for(int o=16;o;o>>=1){
      #pragma unroll
      for(int h=0;h<NH;h++){
        ps[h]+=__shfl_xor_sync(0xffffffffu,ps[h],o);
        pd[h]+=__shfl_xor_sync(0xffffffffu,pd[h],o);
      }
    }
    if(lane==0){
      g_es[row0+r]=make_float4(ps[0],ps[1],ps[2],ps[3]);
      g_ed[row0+r]=make_float4(pd[0],pd[1],pd[2],pd[3]);
    }
  }
}

// ---------------- reset scratch for one GAT layer --------------------------
__global__ void k_reset(){
  int i=blockIdx.x*blockDim.x+threadIdx.x;
  if(i<NN*HID) g_agg[i]=0.f;
  if(i<NN*NH){ g_den[i]=0.f; g_m[i]=0u; }
}

// ---------------- edge pass 1: segment max ---------------------------------
__global__ void k_edge_max(const int* __restrict__ ei){
  int i=blockIdx.x*blockDim.x+threadIdx.x;
  if(i>=ETOT) return;
  int s,d;
  if(i<EE){ s=clampN(ei[i]); d=clampN(ei[EE+i]); } else { s=d=i-EE; }
  float4 es=g_es[s], ed=g_ed[d];
  atomicMax(&g_m[d*4+0], f2o(lrelu(es.x+ed.x)));
  atomicMax(&g_m[d*4+1], f2o(lrelu(es.y+ed.y)));
  atomicMax(&g_m[d*4+2], f2o(lrelu(es.z+ed.z)));
  atomicMax(&g_m[d*4+3], f2o(lrelu(es.w+ed.w)));
}

// ---------------- edge pass 2: segment sum of exp --------------------------
__global__ void k_edge_sum(const int* __restrict__ ei){
  int i=blockIdx.x*blockDim.x+threadIdx.x;
  if(i>=ETOT) return;
  int s,d;
  if(i<EE){ s=clampN(ei[i]); d=clampN(ei[EE+i]); } else { s=d=i-EE; }
  float4 es=g_es[s], ed=g_ed[d];
  atomicAdd(&g_den[d*4+0], expf(lrelu(es.x+ed.x)-o2f(g_m[d*4+0])));
  atomicAdd(&g_den[d*4+1], expf(lrelu(es.y+ed.y)-o2f(g_m[d*4+1])));
  atomicAdd(&g_den[d*4+2], expf(lrelu(es.z+ed.z)-o2f(g_m[d*4+2])));
  atomicAdd(&g_den[d*4+3], expf(lrelu(es.w+ed.w)-o2f(g_m[d*4+3])));
}

// ---------------- edge pass 3: alpha * hW[src] scatter ---------------------
// warp per edge; lane l handles 4 floats (head = l/8); float4 vector atomics.
__global__ void __launch_bounds__(256) k_edge_agg(const int* __restrict__ ei){
  int gw=(blockIdx.x*blockDim.x+threadIdx.x)>>5;
  int lane=threadIdx.x&31;
  if(gw>=ETOT) return;
  int s,d;
  if(gw<EE){ s=clampN(ei[gw]); d=clampN(ei[EE+gw]); } else { s=d=gw-EE; }
  int h=lane>>3;
  float es=((const float*)g_es)[s*4+h];
  float ed=((const float*)g_ed)[d*4+h];
  float e=lrelu(es+ed);
  float m=o2f(g_m[d*4+h]);
  float den=g_den[d*4+h];
  float alpha=expf(e-m)/den;
  float4 v=*(const float4*)&g_hW[s*HID+lane*4];
  v.x*=alpha; v.y*=alpha; v.z*=alpha; v.w*=alpha;
  atomicAdd((float4*)&g_agg[d*HID+lane*4], v);
}

// ---------------- between layers: h = gelu(LN(agg + bg)) -------------------
__global__ void __launch_bounds__(256) k_mid(
    const float* __restrict__ bg, const float* __restrict__ gam,
    const float* __restrict__ bet)
{
  int row=(blockIdx.x*blockDim.x+threadIdx.x)>>5;
  int lane=threadIdx.x&31;
  if(row>=NN) return;
  float4 v=*(float4*)&g_agg[row*HID+lane*4];
  float4 b4=*(const float4*)&bg[lane*4];
  v.x+=b4.x; v.y+=b4.y; v.z+=b4.z; v.w+=b4.w;
  float s=v.x+v.y+v.z+v.w;
  float q=v.x*v.x+v.y*v.y+v.z*v.z+v.w*v.w;
  #pragma unroll
  for(int o=16;o;o>>=1){
    s+=__shfl_xor_sync(0xffffffffu,s,o);
    q+=__shfl_xor_sync(0xffffffffu,q,o);
  }
  float mu=s*(1.f/HID);
  float rs=rsqrtf(q*(1.f/HID)-mu*mu+EPS);
  float4 gg=*(const float4*)&gam[lane*4];
  float4 b2=*(const float4*)&bet[lane*4];
  v.x=gelu_f((v.x-mu)*rs*gg.x+b2.x);
  v.y=gelu_f((v.y-mu)*rs*gg.y+b2.y);
  v.z=gelu_f((v.z-mu)*rs*gg.z+b2.z);
  v.w=gelu_f((v.w-mu)*rs*gg.w+b2.w);
  *(float4*)&g_h[row*HID+lane*4]=v;
}

// ---------------- final: out = (agg + bg2) @ w_out + b_out -----------------
// 128 threads, 32 rows/block; cg = 16 col groups (64 cols), rg = 8 row groups.
__global__ void __launch_bounds__(128) k_out(
    const float* __restrict__ bg, const float* __restrict__ w,
    const float* __restrict__ bo, float* __restrict__ out)
{
  __shared__ float ws[HID*OUTD];  // 32 KB
  __shared__ float hs[32*HID];    // 16 KB
  const int t=threadIdx.x;
  const int row0=blockIdx.x*32;
  const int nrows=min(32, NN-row0);

  for(int i=t;i<HID*OUTD;i+=128) ws[i]=w[i];
  for(int i=t;i<32*HID;i+=128){
    int r=i>>7;
    hs[i]=(r<nrows)? g_agg[row0*HID+i]+bg[i&127] : 0.f;
  }
  __syncthreads();

  const int cg=t&15, rg=t>>4;     // cols 4*cg.., rows rg*4..rg*4+3
  float acc[4][4];
  #pragma unroll
  for(int r=0;r<4;r++){acc[r][0]=0;acc[r][1]=0;acc[r][2]=0;acc[r][3]=0;}

  for(int k=0;k<HID;k++){
    float4 wv=*(float4*)&ws[k*OUTD+4*cg];
    #pragma unroll
    for(int r=0;r<4;r++){
      float hv=hs[(rg*4+r)*HID+k];
      acc[r][0]+=hv*wv.x; acc[r][1]+=hv*wv.y; acc[r][2]+=hv*wv.z; acc[r][3]+=hv*wv.w;
    }
  }
  float4 b4=*(const float4*)&bo[4*cg];
  #pragma unroll
  for(int r=0;r<4;r++){
    int row=row0+rg*4+r;
    if(row<NN)
      *(float4*)&out[row*OUTD+4*cg]=
        make_float4(acc[r][0]+b4.x,acc[r][1]+b4.y,acc[r][2]+b4.z,acc[r][3]+b4.w);
  }
}

// ---------------- launch ----------------------------------------------------
extern "C" void kernel_launch(void* const* d_in, const int* in_sizes, int n_in,
                              void* d_out, int out_size)
{
  const float* x    =(const float*)d_in[0];
  const int*   ei   =(const int*)d_in[1];     // JAX x64 disabled -> int32
  const float* w_in =(const float*)d_in[2];
  const float* b_in =(const float*)d_in[3];
  const float* g1   =(const float*)d_in[4];
  const float* be1  =(const float*)d_in[5];
  const float* W1   =(const float*)d_in[6];
  const float* as1  =(const float*)d_in[7];
  const float* ad1  =(const float*)d_in[8];
  const float* bg1  =(const float*)d_in[9];
  const float* g2   =(const float*)d_in[10];
  const float* be2  =(const float*)d_in[11];
  const float* W2   =(const float*)d_in[12];
  const float* as2  =(const float*)d_in[13];
  const float* ad2  =(const float*)d_in[14];
  const float* bg2  =(const float*)d_in[15];
  const float* w_out=(const float*)d_in[16];
  const float* b_out=(const float*)d_in[17];
  float* out=(float*)d_out;

  const size_t shw=(HID*HID+32*HID+32*HID)*sizeof(float); // 96 KB
  cudaFuncSetAttribute(k_hw, cudaFuncAttributeMaxDynamicSharedMemorySize,(int)shw);

  const int gHW   =(NN+31)/32;
  const int gRST  =(NN*HID+255)/256;
  const int gEDGE =(ETOT+255)/256;
  const int gAGG  =(ETOT+7)/8;        // warp per edge, 8 warps/block
  const int gMID  =(NN+7)/8;

  k_in<<<NN/16,128>>>(x,w_in,b_in,g1,be1);

  // ---- GAT layer 1
  k_hw<<<gHW,128,shw>>>(W1,as1,ad1);
  k_reset<<<gRST,256>>>();
  k_edge_max<<<gEDGE,256>>>(ei);
  k_edge_sum<<<gEDGE,256>>>(ei);
  k_edge_agg<<<gAGG,256>>>(ei);
  k_mid<<<gMID,256>>>(bg1,g2,be2);

  // ---- GAT layer 2
  k_hw<<<gHW,128,shw>>>(W2,as2,ad2);
  k_reset<<<gRST,256>>>();
  k_edge_max<<<gEDGE,256>>>(ei);
  k_edge_sum<<<gEDGE,256>>>(ei);
  k_edge_agg<<<gAGG,256>>>(ei);

  k_out<<<gHW,128>>>(bg2,w_out,b_out,out);
}

// round 4
// speedup vs baseline: 1.1264x; 1.1264x over previous
#include <cuda_runtime.h>
#include <math.h>

#define NN   50000
#define EE   1600000
#define ETOT (EE+NN)
#define IND  64
#define HID  128
#define NH   4
#define HD   32
#define OUTD 64
#define EPS  1e-5f

// ---------------- scratch (device globals; no allocation allowed) ----------
__device__ __align__(16) float    g_h  [NN*HID];   // activations between stages
__device__ __align__(16) float    g_hW [NN*HID];   // h @ W per GAT layer
__device__ __align__(16) float    g_agg[NN*HID];   // unnormalized aggregation
__device__ __align__(16) float4   g_es [NN];       // per-node per-head src score
__device__ __align__(16) float4   g_ed [NN];       // per-node per-head dst score
__device__ float    g_den[NN*NH];                  // softmax denominator

// ---------------- helpers --------------------------------------------------
__device__ __forceinline__ float gelu_f(float x){
  return 0.5f*x*(1.f+tanhf(0.7978845608028654f*(x+0.044715f*x*x*x)));
}
__device__ __forceinline__ float lrelu(float x){ return x>0.f ? x : 0.2f*x; }
__device__ __forceinline__ int clampN(int v){
  return v<0?0:(v>=NN?NN-1:v);
}

// ---------------- stage 1: h = gelu(LN(x @ w_in + b_in)) -------------------
__global__ void __launch_bounds__(128) k_in(
    const float* __restrict__ x, const float* __restrict__ w,
    const float* __restrict__ b, const float* __restrict__ gam,
    const float* __restrict__ bet)
{
  __shared__ float ws[IND*HID];   // 32 KB
  __shared__ float xs[16*IND];    //  4 KB
  __shared__ float hb[16*HID];    //  8 KB
  const int t = threadIdx.x;
  const int row0 = blockIdx.x*16;   // 50000/16 = 3125 exact

  for(int i=t;i<IND*HID;i+=128) ws[i]=w[i];
  for(int i=t;i<16*IND;i+=128)  xs[i]=x[row0*IND+i];
  __syncthreads();

  const int cg=t&31, rg=t>>5;       // cols 4*cg..4*cg+3, rows rg*4..rg*4+3
  float4 bb=*(const float4*)&b[4*cg];
  float acc[4][4];
  #pragma unroll
  for(int r=0;r<4;r++){acc[r][0]=bb.x;acc[r][1]=bb.y;acc[r][2]=bb.z;acc[r][3]=bb.w;}

  for(int k=0;k<IND;k++){
    float4 wv=*(float4*)&ws[k*HID+4*cg];
    #pragma unroll
    for(int r=0;r<4;r++){
      float hv=xs[(rg*4+r)*IND+k];
      acc[r][0]+=hv*wv.x; acc[r][1]+=hv*wv.y; acc[r][2]+=hv*wv.z; acc[r][3]+=hv*wv.w;
    }
  }
  #pragma unroll
  for(int r=0;r<4;r++)
    *(float4*)&hb[(rg*4+r)*HID+4*cg]=make_float4(acc[r][0],acc[r][1],acc[r][2],acc[r][3]);
  __syncthreads();

  const int lane=t&31, wid=t>>5;
  float4 gg=*(const float4*)&gam[lane*4];
  float4 b2=*(const float4*)&bet[lane*4];
  for(int r=wid;r<16;r+=4){
    float4 v=*(float4*)&hb[r*HID+lane*4];
    float s=v.x+v.y+v.z+v.w;
    float q=v.x*v.x+v.y*v.y+v.z*v.z+v.w*v.w;
    #pragma unroll
    for(int o=16;o;o>>=1){
      s+=__shfl_xor_sync(0xffffffffu,s,o);
      q+=__shfl_xor_sync(0xffffffffu,q,o);
    }
    float mu=s*(1.f/HID);
    float rs=rsqrtf(q*(1.f/HID)-mu*mu+EPS);
    v.x=gelu_f((v.x-mu)*rs*gg.x+b2.x);
    v.y=gelu_f((v.y-mu)*rs*gg.y+b2.y);
    v.z=gelu_f((v.z-mu)*rs*gg.z+b2.z);
    v.w=gelu_f((v.w-mu)*rs*gg.w+b2.w);
    *(float4*)&g_h[(row0+r)*HID+lane*4]=v;
  }
}

// ---------------- stage 2: hW = h @ W ; e_src/e_dst ------------------------
__global__ void __launch_bounds__(128) k_hw(
    const float* __restrict__ W, const float* __restrict__ asrc,
    const float* __restrict__ adst)
{
  extern __shared__ float sm[];
  float* Ws  = sm;                 // 64 KB
  float* hs  = sm + HID*HID;       // 16 KB
  float* hwb = hs + 32*HID;        // 16 KB
  const int t = threadIdx.x;
  const int row0 = blockIdx.x*32;
  const int nrows = min(32, NN-row0);

  for(int i=t;i<HID*HID;i+=128) Ws[i]=W[i];
  for(int i=t;i<nrows*HID;i+=128) hs[i]=g_h[row0*HID+i];
  for(int i=nrows*HID+t;i<32*HID;i+=128) hs[i]=0.f;
  __syncthreads();

  const int cg=t&31, rg=t>>5;      // cols 4*cg.., rows rg*8..rg*8+7
  float acc[8][4];
  #pragma unroll
  for(int r=0;r<8;r++){acc[r][0]=0;acc[r][1]=0;acc[r][2]=0;acc[r][3]=0;}

  for(int k=0;k<HID;k++){
    float4 wv=*(float4*)&Ws[k*HID+4*cg];
    #pragma unroll
    for(int r=0;r<8;r++){
      float hv=hs[(rg*8+r)*HID+k];
      acc[r][0]+=hv*wv.x; acc[r][1]+=hv*wv.y; acc[r][2]+=hv*wv.z; acc[r][3]+=hv*wv.w;
    }
  }
  #pragma unroll
  for(int r=0;r<8;r++)
    *(float4*)&hwb[(rg*8+r)*HID+4*cg]=make_float4(acc[r][0],acc[r][1],acc[r][2],acc[r][3]);
  __syncthreads();

  for(int i=t;i<nrows*HID;i+=128) g_hW[row0*HID+i]=hwb[i];

  const int lane=t&31, wid=t>>5;
  for(int r=wid;r<nrows;r+=4){
    float ps[NH], pd[NH];
    #pragma unroll
    for(int h=0;h<NH;h++){
      float v=hwb[r*HID+h*HD+lane];
      ps[h]=v*asrc[h*HD+lane];
      pd[h]=v*adst[h*HD+lane];
    }
    #pragma unroll
    for(int o=16;o;o>>=1){
      #pragma unroll
      for(int h=0;h<NH;h++){
        ps[h]+=__shfl_xor_sync(0xffffffffu,ps[h],o);
        pd[h]+=__shfl_xor_sync(0xffffffffu,pd[h],o);
      }
    }
    if(lane==0){
      g_es[row0+r]=make_float4(ps[0],ps[1],ps[2],ps[3]);
      g_ed[row0+r]=make_float4(pd[0],pd[1],pd[2],pd[3]);
    }
  }
}

// ---------------- reset scratch for one GAT layer --------------------------
__global__ void k_reset(){
  int i=blockIdx.x*blockDim.x+threadIdx.x;
  if(i<NN*HID) g_agg[i]=0.f;
  if(i<NN*NH) g_den[i]=0.f;
}

// ---------------- fused edge pass: w=exp(lrelu(es+ed)); scatter ------------
// out[d] = sum_e w*hW[src]  (unnormalized); den[d] = sum_e w.
// warp per edge; lane l handles 4 floats (head = l/8); float4 vector atomics.
__global__ void __launch_bounds__(256) k_edge_agg(const int* __restrict__ ei){
  int gw=(blockIdx.x*blockDim.x+threadIdx.x)>>5;
  int lane=threadIdx.x&31;
  if(gw>=ETOT) return;
  int s,d;
  if(gw<EE){ s=clampN(ei[gw]); d=clampN(ei[EE+gw]); } else { s=d=gw-EE; }
  int h=lane>>3;
  float es=((const float*)g_es)[s*4+h];
  float ed=((const float*)g_ed)[d*4+h];
  float w=__expf(lrelu(es+ed));
  if((lane&7)==0) atomicAdd(&g_den[d*4+h], w);
  float4 v=*(const float4*)&g_hW[s*HID+lane*4];
  v.x*=w; v.y*=w; v.z*=w; v.w*=w;
  atomicAdd((float4*)&g_agg[d*HID+lane*4], v);
}

// ---------------- between layers: h = gelu(LN(agg/den + bg)) ---------------
__global__ void __launch_bounds__(256) k_mid(
    const float* __restrict__ bg, const float* __restrict__ gam,
    const float* __restrict__ bet)
{
  int row=(blockIdx.x*blockDim.x+threadIdx.x)>>5;
  int lane=threadIdx.x&31;
  if(row>=NN) return;
  float inv=1.f/g_den[row*4+(lane>>3)];
  float4 v=*(float4*)&g_agg[row*HID+lane*4];
  float4 b4=*(const float4*)&bg[lane*4];
  v.x=v.x*inv+b4.x; v.y=v.y*inv+b4.y; v.z=v.z*inv+b4.z; v.w=v.w*inv+b4.w;
  float s=v.x+v.y+v.z+v.w;
  float q=v.x*v.x+v.y*v.y+v.z*v.z+v.w*v.w;
  #pragma unroll
  for(int o=16;o;o>>=1){
    s+=__shfl_xor_sync(0xffffffffu,s,o);
    q+=__shfl_xor_sync(0xffffffffu,q,o);
  }
  float mu=s*(1.f/HID);
  float rs=rsqrtf(q*(1.f/HID)-mu*mu+EPS);
  float4 gg=*(const float4*)&gam[lane*4];
  float4 b2=*(const float4*)&bet[lane*4];
  v.x=gelu_f((v.x-mu)*rs*gg.x+b2.x);
  v.y=gelu_f((v.y-mu)*rs*gg.y+b2.y);
  v.z=gelu_f((v.z-mu)*rs*gg.z+b2.z);
  v.w=gelu_f((v.w-mu)*rs*gg.w+b2.w);
  *(float4*)&g_h[row*HID+lane*4]=v;
}

// ---------------- final: out = (agg/den + bg2) @ w_out + b_out -------------
__global__ void __launch_bounds__(128) k_out(
    const float* __restrict__ bg, const float* __restrict__ w,
    const float* __restrict__ bo, float* __restrict__ out)
{
  __shared__ float ws[HID*OUTD];  // 32 KB
  __shared__ float hs[32*HID];    // 16 KB
  const int t=threadIdx.x;
  const int row0=blockIdx.x*32;
  const int nrows=min(32, NN-row0);

  for(int i=t;i<HID*OUTD;i+=128) ws[i]=w[i];
  for(int i=t;i<32*HID;i+=128){
    int r=i>>7, c=i&127;
    float v=0.f;
    if(r<nrows){
      float inv=1.f/g_den[(row0+r)*4+(c>>5)];
      v=g_agg[row0*HID+i]*inv+bg[c];
    }
    hs[i]=v;
  }
  __syncthreads();

  const int cg=t&15, rg=t>>4;     // cols 4*cg.., rows rg*4..rg*4+3
  float acc[4][4];
  #pragma unroll
  for(int r=0;r<4;r++){acc[r][0]=0;acc[r][1]=0;acc[r][2]=0;acc[r][3]=0;}

  for(int k=0;k<HID;k++){
    float4 wv=*(float4*)&ws[k*OUTD+4*cg];
    #pragma unroll
    for(int r=0;r<4;r++){
      float hv=hs[(rg*4+r)*HID+k];
      acc[r][0]+=hv*wv.x; acc[r][1]+=hv*wv.y; acc[r][2]+=hv*wv.z; acc[r][3]+=hv*wv.w;
    }
  }
  float4 b4=*(const float4*)&bo[4*cg];
  #pragma unroll
  for(int r=0;r<4;r++){
    int row=row0+rg*4+r;
    if(row<NN)
      *(float4*)&out[row*OUTD+4*cg]=
        make_float4(acc[r][0]+b4.x,acc[r][1]+b4.y,acc[r][2]+b4.z,acc[r][3]+b4.w);
  }
}

// ---------------- launch ----------------------------------------------------
extern "C" void kernel_launch(void* const* d_in, const int* in_sizes, int n_in,
                              void* d_out, int out_size)
{
  const float* x    =(const float*)d_in[0];
  const int*   ei   =(const int*)d_in[1];     // int32 edge index
  const float* w_in =(const float*)d_in[2];
  const float* b_in =(const float*)d_in[3];
  const float* g1   =(const float*)d_in[4];
  const float* be1  =(const float*)d_in[5];
  const float* W1   =(const float*)d_in[6];
  const float* as1  =(const float*)d_in[7];
  const float* ad1  =(const float*)d_in[8];
  const float* bg1  =(const float*)d_in[9];
  const float* g2   =(const float*)d_in[10];
  const float* be2  =(const float*)d_in[11];
  const float* W2   =(const float*)d_in[12];
  const float* as2  =(const float*)d_in[13];
  const float* ad2  =(const float*)d_in[14];
  const float* bg2  =(const float*)d_in[15];
  const float* w_out=(const float*)d_in[16];
  const float* b_out=(const float*)d_in[17];
  float* out=(float*)d_out;

  const size_t shw=(HID*HID+32*HID+32*HID)*sizeof(float); // 96 KB
  cudaFuncSetAttribute(k_hw, cudaFuncAttributeMaxDynamicSharedMemorySize,(int)shw);

  const int gHW   =(NN+31)/32;
  const int gRST  =(NN*HID+255)/256;
  const int gAGG  =(ETOT+7)/8;        // warp per edge, 8 warps/block
  const int gMID  =(NN+7)/8;

  k_in<<<NN/16,128>>>(x,w_in,b_in,g1,be1);

  // ---- GAT layer 1
  k_hw<<<gHW,128,shw>>>(W1,as1,ad1);
  k_reset<<<gRST,256>>>();
  k_edge_agg<<<gAGG,256>>>(ei);
  k_mid<<<gMID,256>>>(bg1,g2,be2);

  // ---- GAT layer 2
  k_hw<<<gHW,128,shw>>>(W2,as2,ad2);
  k_reset<<<gRST,256>>>();
  k_edge_agg<<<gAGG,256>>>(ei);

  k_out<<<gHW,128>>>(bg2,w_out,b_out,out);
}

// round 8
// speedup vs baseline: 1.7136x; 1.5213x over previous
#include <cuda_runtime.h>
#include <math.h>

#define NN   50000
#define EE   1600000
#define ETOT (EE+NN)
#define IND  64
#define HID  128
#define NH   4
#define HD   32
#define OUTD 64
#define EPS  1e-5f

// ---------------- scratch (device globals; no allocation allowed) ----------
__device__ __align__(16) float    g_h  [NN*HID];   // activations between stages
__device__ __align__(16) float    g_hW [NN*HID];   // h @ W per GAT layer
__device__ __align__(16) float    g_agg[NN*HID];   // normalized aggregation (layer2)
__device__ __align__(16) float4   g_es [NN];       // per-node per-head src score
__device__ __align__(16) float4   g_ed [NN];       // per-node per-head dst score
__device__ int g_cnt   [NN];                       // CSR: per-dst degree
__device__ int g_rowptr[NN+1];                     // CSR: row pointers
__device__ int g_pos   [NN];                       // CSR: scatter cursors
__device__ int g_csrc  [ETOT];                     // CSR: src id per slot

// ---------------- helpers --------------------------------------------------
__device__ __forceinline__ float gelu_f(float x){
  return 0.5f*x*(1.f+tanhf(0.7978845608028654f*(x+0.044715f*x*x*x)));
}
__device__ __forceinline__ float lrelu(float x){ return x>0.f ? x : 0.2f*x; }
__device__ __forceinline__ int clampN(int v){
  return v<0?0:(v>=NN?NN-1:v);
}

// ---------------- stage 1: h = gelu(LN(x @ w_in + b_in)) -------------------
__global__ void __launch_bounds__(128) k_in(
    const float* __restrict__ x, const float* __restrict__ w,
    const float* __restrict__ b, const float* __restrict__ gam,
    const float* __restrict__ bet)
{
  __shared__ float ws[IND*HID];   // 32 KB
  __shared__ float xs[16*IND];    //  4 KB
  __shared__ float hb[16*HID];    //  8 KB
  const int t = threadIdx.x;
  const int row0 = blockIdx.x*16;   // 50000/16 = 3125 exact

  for(int i=t;i<IND*HID;i+=128) ws[i]=w[i];
  for(int i=t;i<16*IND;i+=128)  xs[i]=x[row0*IND+i];
  __syncthreads();

  const int cg=t&31, rg=t>>5;
  float4 bb=*(const float4*)&b[4*cg];
  float acc[4][4];
  #pragma unroll
  for(int r=0;r<4;r++){acc[r][0]=bb.x;acc[r][1]=bb.y;acc[r][2]=bb.z;acc[r][3]=bb.w;}

  for(int k=0;k<IND;k++){
    float4 wv=*(float4*)&ws[k*HID+4*cg];
    #pragma unroll
    for(int r=0;r<4;r++){
      float hv=xs[(rg*4+r)*IND+k];
      acc[r][0]+=hv*wv.x; acc[r][1]+=hv*wv.y; acc[r][2]+=hv*wv.z; acc[r][3]+=hv*wv.w;
    }
  }
  #pragma unroll
  for(int r=0;r<4;r++)
    *(float4*)&hb[(rg*4+r)*HID+4*cg]=make_float4(acc[r][0],acc[r][1],acc[r][2],acc[r][3]);
  __syncthreads();

  const int lane=t&31, wid=t>>5;
  float4 gg=*(const float4*)&gam[lane*4];
  float4 b2=*(const float4*)&bet[lane*4];
  for(int r=wid;r<16;r+=4){
    float4 v=*(float4*)&hb[r*HID+lane*4];
    float s=v.x+v.y+v.z+v.w;
    float q=v.x*v.x+v.y*v.y+v.z*v.z+v.w*v.w;
    #pragma unroll
    for(int o=16;o;o>>=1){
      s+=__shfl_xor_sync(0xffffffffu,s,o);
      q+=__shfl_xor_sync(0xffffffffu,q,o);
    }
    float mu=s*(1.f/HID);
    float rs=rsqrtf(q*(1.f/HID)-mu*mu+EPS);
    v.x=gelu_f((v.x-mu)*rs*gg.x+b2.x);
    v.y=gelu_f((v.y-mu)*rs*gg.y+b2.y);
    v.z=gelu_f((v.z-mu)*rs*gg.z+b2.z);
    v.w=gelu_f((v.w-mu)*rs*gg.w+b2.w);
    *(float4*)&g_h[(row0+r)*HID+lane*4]=v;
  }
}

// ---------------- stage 2: hW = h @ W ; e_src/e_dst ------------------------
__global__ void __launch_bounds__(128) k_hw(
    const float* __restrict__ W, const float* __restrict__ asrc,
    const float* __restrict__ adst)
{
  extern __shared__ float sm[];
  float* Ws  = sm;                 // 64 KB
  float* hs  = sm + HID*HID;       // 16 KB
  float* hwb = hs + 32*HID;        // 16 KB
  const int t = threadIdx.x;
  const int row0 = blockIdx.x*32;
  const int nrows = min(32, NN-row0);

  for(int i=t;i<HID*HID;i+=128) Ws[i]=W[i];
  for(int i=t;i<nrows*HID;i+=128) hs[i]=g_h[row0*HID+i];
  for(int i=nrows*HID+t;i<32*HID;i+=128) hs[i]=0.f;
  __syncthreads();

  const int cg=t&31, rg=t>>5;
  float acc[8][4];
  #pragma unroll
  for(int r=0;r<8;r++){acc[r][0]=0;acc[r][1]=0;acc[r][2]=0;acc[r][3]=0;}

  for(int k=0;k<HID;k++){
    float4 wv=*(float4*)&Ws[k*HID+4*cg];
    #pragma unroll
    for(int r=0;r<8;r++){
      float hv=hs[(rg*8+r)*HID+k];
      acc[r][0]+=hv*wv.x; acc[r][1]+=hv*wv.y; acc[r][2]+=hv*wv.z; acc[r][3]+=hv*wv.w;
    }
  }
  #pragma unroll
  for(int r=0;r<8;r++)
    *(float4*)&hwb[(rg*8+r)*HID+4*cg]=make_float4(acc[r][0],acc[r][1],acc[r][2],acc[r][3]);
  __syncthreads();

  for(int i=t;i<nrows*HID;i+=128) g_hW[row0*HID+i]=hwb[i];

  const int lane=t&31, wid=t>>5;
  for(int r=wid;r<nrows;r+=4){
    float ps[NH], pd[NH];
    #pragma unroll
    for(int h=0;h<NH;h++){
      float v=hwb[r*HID+h*HD+lane];
      ps[h]=v*asrc[h*HD+lane];
      pd[h]=v*adst[h*HD+lane];
    }
    #pragma unroll
    for(int o=16;o;o>>=1){
      #pragma unroll
      for(int h=0;h<NH;h++){
        ps[h]+=__shfl_xor_sync(0xffffffffu,ps[h],o);
        pd[h]+=__shfl_xor_sync(0xffffffffu,pd[h],o);
      }
    }
    if(lane==0){
      g_es[row0+r]=make_float4(ps[0],ps[1],ps[2],ps[3]);
      g_ed[row0+r]=make_float4(pd[0],pd[1],pd[2],pd[3]);
    }
  }
}

// ---------------- CSR build (once; reused by both layers) ------------------
__global__ void k_zero_cnt(){
  int i=blockIdx.x*blockDim.x+threadIdx.x;
  if(i<NN) g_cnt[i]=0;
}
__global__ void k_hist(const int* __restrict__ ei){
  int i=blockIdx.x*blockDim.x+threadIdx.x;
  if(i>=ETOT) return;
  int d = (i<EE)? clampN(ei[EE+i]) : i-EE;
  atomicAdd(&g_cnt[d],1);
}
__global__ void __launch_bounds__(1024) k_scan(){
  __shared__ int part[1024];
  const int t=threadIdx.x;
  const int CH=(NN+1023)/1024;           // 49
  int b=t*CH, e=min(b+CH,NN);
  int s=0;
  for(int i=b;i<e;i++) s+=g_cnt[i];
  part[t]=s; __syncthreads();
  for(int off=1;off<1024;off<<=1){
    int v=(t>=off)? part[t-off] : 0;
    __syncthreads();
    part[t]+=v;
    __syncthreads();
  }
  int run=(t==0)?0:part[t-1];
  for(int i=b;i<e;i++){
    g_rowptr[i]=run; g_pos[i]=run; run+=g_cnt[i];
  }
  if(t==1023) g_rowptr[NN]=ETOT;
}
__global__ void k_scatter(const int* __restrict__ ei){
  int i=blockIdx.x*blockDim.x+threadIdx.x;
  if(i>=ETOT) return;
  int s,d;
  if(i<EE){ s=clampN(ei[i]); d=clampN(ei[EE+i]); } else { s=d=i-EE; }
  int p=atomicAdd(&g_pos[d],1);
  g_csrc[p]=s;
}

// ---------------- fused aggregation: warp per dst node ---------------------
// acc = sum_e exp(lrelu(es[s]+ed[d])) * hW[s]; den = sum_e w; all in regs.
// FUSE_LN: apply /den + bg + LN + gelu -> g_h (between-layer path).
// else:    write acc/den -> g_agg (k_out adds bg).
template<bool FUSE_LN>
__global__ void __launch_bounds__(256) k_agg(
    const float* __restrict__ bg, const float* __restrict__ gam,
    const float* __restrict__ bet)
{
  int node=(blockIdx.x*blockDim.x+threadIdx.x)>>5;
  int lane=threadIdx.x&31;
  if(node>=NN) return;
  const int h=lane>>3;
  const int beg=g_rowptr[node], end=g_rowptr[node+1];
  const float edv=((const float*)g_ed)[node*4+h];

  float4 acc=make_float4(0.f,0.f,0.f,0.f);
  float den=0.f;
  for(int j=beg;j<end;j++){
    int s=g_csrc[j];
    float w=__expf(lrelu(((const float*)g_es)[s*4+h]+edv));
    float4 v=*(const float4*)&g_hW[s*HID+lane*4];
    acc.x+=w*v.x; acc.y+=w*v.y; acc.z+=w*v.z; acc.w+=w*v.w;
    den+=w;
  }
  float inv=1.f/den;
  float4 b4=*(const float4*)&bg[lane*4];
  float4 v;
  v.x=acc.x*inv; v.y=acc.y*inv; v.z=acc.z*inv; v.w=acc.w*inv;

  if(FUSE_LN){
    v.x+=b4.x; v.y+=b4.y; v.z+=b4.z; v.w+=b4.w;
    float s=v.x+v.y+v.z+v.w;
    float q=v.x*v.x+v.y*v.y+v.z*v.z+v.w*v.w;
    #pragma unroll
    for(int o=16;o;o>>=1){
      s+=__shfl_xor_sync(0xffffffffu,s,o);
      q+=__shfl_xor_sync(0xffffffffu,q,o);
    }
    float mu=s*(1.f/HID);
    float rs=rsqrtf(q*(1.f/HID)-mu*mu+EPS);
    float4 gg=*(const float4*)&gam[lane*4];
    float4 b2=*(const float4*)&bet[lane*4];
    v.x=gelu_f((v.x-mu)*rs*gg.x+b2.x);
    v.y=gelu_f((v.y-mu)*rs*gg.y+b2.y);
    v.z=gelu_f((v.z-mu)*rs*gg.z+b2.z);
    v.w=gelu_f((v.w-mu)*rs*gg.w+b2.w);
    *(float4*)&g_h[node*HID+lane*4]=v;
  }else{
    *(float4*)&g_agg[node*HID+lane*4]=v;
  }
}

// ---------------- final: out = (agg + bg2) @ w_out + b_out -----------------
__global__ void __launch_bounds__(128) k_out(
    const float* __restrict__ bg, const float* __restrict__ w,
    const float* __restrict__ bo, float* __restrict__ out)
{
  __shared__ float ws[HID*OUTD];  // 32 KB
  __shared__ float hs[32*HID];    // 16 KB
  const int t=threadIdx.x;
  const int row0=blockIdx.x*32;
  const int nrows=min(32, NN-row0);

  for(int i=t;i<HID*OUTD;i+=128) ws[i]=w[i];
  for(int i=t;i<32*HID;i+=128){
    int r=i>>7, c=i&127;
    hs[i]=(r<nrows)? g_agg[row0*HID+i]+bg[c] : 0.f;
  }
  __syncthreads();

  const int cg=t&15, rg=t>>4;
  float acc[4][4];
  #pragma unroll
  for(int r=0;r<4;r++){acc[r][0]=0;acc[r][1]=0;acc[r][2]=0;acc[r][3]=0;}

  for(int k=0;k<HID;k++){
    float4 wv=*(float4*)&ws[k*OUTD+4*cg];
    #pragma unroll
    for(int r=0;r<4;r++){
      float hv=hs[(rg*4+r)*HID+k];
      acc[r][0]+=hv*wv.x; acc[r][1]+=hv*wv.y; acc[r][2]+=hv*wv.z; acc[r][3]+=hv*wv.w;
    }
  }
  float4 b4=*(const float4*)&bo[4*cg];
  #pragma unroll
  for(int r=0;r<4;r++){
    int row=row0+rg*4+r;
    if(row<NN)
      *(float4*)&out[row*OUTD+4*cg]=
        make_float4(acc[r][0]+b4.x,acc[r][1]+b4.y,acc[r][2]+b4.z,acc[r][3]+b4.w);
  }
}

// ---------------- launch ----------------------------------------------------
extern "C" void kernel_launch(void* const* d_in, const int* in_sizes, int n_in,
                              void* d_out, int out_size)
{
  const float* x    =(const float*)d_in[0];
  const int*   ei   =(const int*)d_in[1];
  const float* w_in =(const float*)d_in[2];
  const float* b_in =(const float*)d_in[3];
  const float* g1   =(const float*)d_in[4];
  const float* be1  =(const float*)d_in[5];
  const float* W1   =(const float*)d_in[6];
  const float* as1  =(const float*)d_in[7];
  const float* ad1  =(const float*)d_in[8];
  const float* bg1  =(const float*)d_in[9];
  const float* g2   =(const float*)d_in[10];
  const float* be2  =(const float*)d_in[11];
  const float* W2   =(const float*)d_in[12];
  const float* as2  =(const float*)d_in[13];
  const float* ad2  =(const float*)d_in[14];
  const float* bg2  =(const float*)d_in[15];
  const float* w_out=(const float*)d_in[16];
  const float* b_out=(const float*)d_in[17];
  float* out=(float*)d_out;

  const size_t shw=(HID*HID+32*HID+32*HID)*sizeof(float); // 96 KB
  cudaFuncSetAttribute(k_hw, cudaFuncAttributeMaxDynamicSharedMemorySize,(int)shw);

  const int gHW  =(NN+31)/32;
  const int gE   =(ETOT+255)/256;
  const int gN   =(NN+255)/256;
  const int gAGG =(NN*32+255)/256;   // warp per node

  // dense stage 1 + CSR build (CSR independent of features)
  k_in<<<NN/16,128>>>(x,w_in,b_in,g1,be1);
  k_zero_cnt<<<gN,256>>>();
  k_hist<<<gE,256>>>(ei);
  k_scan<<<1,1024>>>();
  k_scatter<<<gE,256>>>(ei);

  // ---- GAT layer 1 (fused agg + LN + gelu)
  k_hw<<<gHW,128,shw>>>(W1,as1,ad1);
  k_agg<true><<<gAGG,256>>>(bg1,g2,be2);

  // ---- GAT layer 2
  k_hw<<<gHW,128,shw>>>(W2,as2,ad2);
  k_agg<false><<<gAGG,256>>>(nullptr,nullptr,nullptr);

  k_out<<<gHW,128>>>(bg2,w_out,b_out,out);
}

// round 9
// speedup vs baseline: 1.9061x; 1.1123x over previous
#include <cuda_runtime.h>
#include <math.h>

#define NN   50000
#define EE   1600000
#define ETOT (EE+NN)
#define IND  64
#define HID  128
#define NH   4
#define HD   32
#define OUTD 64
#define EPS  1e-5f

#define SCAN_B 128   // phase-1 blocks
#define SCAN_T 256   // phase-1 threads/block (each thread: 2 counts)

// ---------------- scratch (device globals; no allocation allowed) ----------
__device__ __align__(16) float    g_h  [NN*HID];   // activations between stages
__device__ __align__(16) float    g_hW [NN*HID];   // h @ W per GAT layer
__device__ __align__(16) float    g_agg[NN*HID];   // normalized aggregation (layer2)
__device__ __align__(16) float4   g_es [NN];       // per-node per-head src score
__device__ __align__(16) float4   g_ed [NN];       // per-node per-head dst score
__device__ int g_cnt   [NN];                       // CSR: per-dst degree
__device__ int g_rowptr[NN+1];                     // CSR: row pointers
__device__ int g_pos   [NN];                       // CSR: scatter cursors
__device__ int g_csrc  [ETOT];                     // CSR: src id per slot
__device__ int g_tpre  [SCAN_B*SCAN_T];            // scan: per-thread prefix
__device__ int g_bsum  [SCAN_B];                   // scan: block totals
__device__ int g_bbase [SCAN_B];                   // scan: block bases

// ---------------- helpers --------------------------------------------------
__device__ __forceinline__ float gelu_f(float x){
  return 0.5f*x*(1.f+tanhf(0.7978845608028654f*(x+0.044715f*x*x*x)));
}
__device__ __forceinline__ float lrelu(float x){ return x>0.f ? x : 0.2f*x; }
__device__ __forceinline__ int clampN(int v){
  return v<0?0:(v>=NN?NN-1:v);
}

// ---------------- stage 1: h = gelu(LN(x @ w_in + b_in)) -------------------
__global__ void __launch_bounds__(128) k_in(
    const float* __restrict__ x, const float* __restrict__ w,
    const float* __restrict__ b, const float* __restrict__ gam,
    const float* __restrict__ bet)
{
  __shared__ float ws[IND*HID];   // 32 KB
  __shared__ float xs[16*IND];    //  4 KB
  __shared__ float hb[16*HID];    //  8 KB
  const int t = threadIdx.x;
  const int row0 = blockIdx.x*16;   // 50000/16 = 3125 exact

  for(int i=t;i<IND*HID;i+=128) ws[i]=w[i];
  for(int i=t;i<16*IND;i+=128)  xs[i]=x[row0*IND+i];
  __syncthreads();

  const int cg=t&31, rg=t>>5;
  float4 bb=*(const float4*)&b[4*cg];
  float acc[4][4];
  #pragma unroll
  for(int r=0;r<4;r++){acc[r][0]=bb.x;acc[r][1]=bb.y;acc[r][2]=bb.z;acc[r][3]=bb.w;}

  for(int k=0;k<IND;k++){
    float4 wv=*(float4*)&ws[k*HID+4*cg];
    #pragma unroll
    for(int r=0;r<4;r++){
      float hv=xs[(rg*4+r)*IND+k];
      acc[r][0]+=hv*wv.x; acc[r][1]+=hv*wv.y; acc[r][2]+=hv*wv.z; acc[r][3]+=hv*wv.w;
    }
  }
  #pragma unroll
  for(int r=0;r<4;r++)
    *(float4*)&hb[(rg*4+r)*HID+4*cg]=make_float4(acc[r][0],acc[r][1],acc[r][2],acc[r][3]);
  __syncthreads();

  const int lane=t&31, wid=t>>5;
  float4 gg=*(const float4*)&gam[lane*4];
  float4 b2=*(const float4*)&bet[lane*4];
  for(int r=wid;r<16;r+=4){
    float4 v=*(float4*)&hb[r*HID+lane*4];
    float s=v.x+v.y+v.z+v.w;
    float q=v.x*v.x+v.y*v.y+v.z*v.z+v.w*v.w;
    #pragma unroll
    for(int o=16;o;o>>=1){
      s+=__shfl_xor_sync(0xffffffffu,s,o);
      q+=__shfl_xor_sync(0xffffffffu,q,o);
    }
    float mu=s*(1.f/HID);
    float rs=rsqrtf(q*(1.f/HID)-mu*mu+EPS);
    v.x=gelu_f((v.x-mu)*rs*gg.x+b2.x);
    v.y=gelu_f((v.y-mu)*rs*gg.y+b2.y);
    v.z=gelu_f((v.z-mu)*rs*gg.z+b2.z);
    v.w=gelu_f((v.w-mu)*rs*gg.w+b2.w);
    *(float4*)&g_h[(row0+r)*HID+lane*4]=v;
  }
}

// ---------------- stage 2: hW = h @ W ; e_src/e_dst ------------------------
__global__ void __launch_bounds__(128) k_hw(
    const float* __restrict__ W, const float* __restrict__ asrc,
    const float* __restrict__ adst)
{
  extern __shared__ float sm[];
  float* Ws  = sm;                 // 64 KB
  float* hs  = sm + HID*HID;       // 16 KB
  float* hwb = hs + 32*HID;        // 16 KB
  const int t = threadIdx.x;
  const int row0 = blockIdx.x*32;
  const int nrows = min(32, NN-row0);

  for(int i=t;i<HID*HID;i+=128) Ws[i]=W[i];
  for(int i=t;i<nrows*HID;i+=128) hs[i]=g_h[row0*HID+i];
  for(int i=nrows*HID+t;i<32*HID;i+=128) hs[i]=0.f;
  __syncthreads();

  const int cg=t&31, rg=t>>5;
  float acc[8][4];
  #pragma unroll
  for(int r=0;r<8;r++){acc[r][0]=0;acc[r][1]=0;acc[r][2]=0;acc[r][3]=0;}

  for(int k=0;k<HID;k++){
    float4 wv=*(float4*)&Ws[k*HID+4*cg];
    #pragma unroll
    for(int r=0;r<8;r++){
      float hv=hs[(rg*8+r)*HID+k];
      acc[r][0]+=hv*wv.x; acc[r][1]+=hv*wv.y; acc[r][2]+=hv*wv.z; acc[r][3]+=hv*wv.w;
    }
  }
  #pragma unroll
  for(int r=0;r<8;r++)
    *(float4*)&hwb[(rg*8+r)*HID+4*cg]=make_float4(acc[r][0],acc[r][1],acc[r][2],acc[r][3]);
  __syncthreads();

  for(int i=t;i<nrows*HID;i+=128) g_hW[row0*HID+i]=hwb[i];

  const int lane=t&31, wid=t>>5;
  for(int r=wid;r<nrows;r+=4){
    float ps[NH], pd[NH];
    #pragma unroll
    for(int h=0;h<NH;h++){
      float v=hwb[r*HID+h*HD+lane];
      ps[h]=v*asrc[h*HD+lane];
      pd[h]=v*adst[h*HD+lane];
    }
    #pragma unroll
    for(int o=16;o;o>>=1){
      #pragma unroll
      for(int h=0;h<NH;h++){
        ps[h]+=__shfl_xor_sync(0xffffffffu,ps[h],o);
        pd[h]+=__shfl_xor_sync(0xffffffffu,pd[h],o);
      }
    }
    if(lane==0){
      g_es[row0+r]=make_float4(ps[0],ps[1],ps[2],ps[3]);
      g_ed[row0+r]=make_float4(pd[0],pd[1],pd[2],pd[3]);
    }
  }
}

// ---------------- CSR build (once; reused by both layers) ------------------
__global__ void k_zero_cnt(){
  int i=blockIdx.x*blockDim.x+threadIdx.x;
  if(i<NN) g_cnt[i]=0;
}
__global__ void k_hist(const int* __restrict__ ei){
  int i=blockIdx.x*blockDim.x+threadIdx.x;
  if(i>=ETOT) return;
  int d = (i<EE)? clampN(ei[EE+i]) : i-EE;
  atomicAdd(&g_cnt[d],1);
}
// 3-phase device-wide exclusive scan of g_cnt -> g_rowptr/g_pos
__global__ void __launch_bounds__(SCAN_T) k_scan1(){
  __shared__ int sh[SCAN_T];
  const int t=threadIdx.x, b=blockIdx.x;
  const int g=b*SCAN_T+t;
  const int i0=g*2;
  int c0=(i0<NN)? g_cnt[i0]:0;
  int c1=(i0+1<NN)? g_cnt[i0+1]:0;
  sh[t]=c0+c1; __syncthreads();
  for(int off=1;off<SCAN_T;off<<=1){
    int v=(t>=off)? sh[t-off]:0; __syncthreads();
    sh[t]+=v; __syncthreads();
  }
  g_tpre[g]=(t==0)?0:sh[t-1];
  if(t==SCAN_T-1) g_bsum[b]=sh[SCAN_T-1];
}
__global__ void __launch_bounds__(SCAN_B) k_scan2(){
  __shared__ int sh[SCAN_B];
  const int t=threadIdx.x;
  sh[t]=g_bsum[t]; __syncthreads();
  for(int off=1;off<SCAN_B;off<<=1){
    int v=(t>=off)? sh[t-off]:0; __syncthreads();
    sh[t]+=v; __syncthreads();
  }
  g_bbase[t]=(t==0)?0:sh[t-1];
}
__global__ void __launch_bounds__(SCAN_T) k_scan3(){
  const int t=threadIdx.x, b=blockIdx.x;
  const int g=b*SCAN_T+t;
  const int i0=g*2;
  int base=g_bbase[b]+g_tpre[g];
  if(i0<NN){
    g_rowptr[i0]=base; g_pos[i0]=base;
    int nb=base+g_cnt[i0];
    if(i0+1<NN){ g_rowptr[i0+1]=nb; g_pos[i0+1]=nb; }
  }
  if(g==0) g_rowptr[NN]=ETOT;
}
__global__ void k_scatter(const int* __restrict__ ei){
  int i=blockIdx.x*blockDim.x+threadIdx.x;
  if(i>=ETOT) return;
  int s,d;
  if(i<EE){ s=clampN(ei[i]); d=clampN(ei[EE+i]); } else { s=d=i-EE; }
  int p=atomicAdd(&g_pos[d],1);
  g_csrc[p]=s;
}

// ---------------- fused aggregation: warp per dst node ---------------------
// acc = sum_e exp(lrelu(es[s]+ed[d])) * hW[s]; den = sum_e w; all in regs.
// 2-way unrolled gather loop for MLP. FUSE_LN: +bias+LN+gelu -> g_h.
template<bool FUSE_LN>
__global__ void __launch_bounds__(256) k_agg(
    const float* __restrict__ bg, const float* __restrict__ gam,
    const float* __restrict__ bet)
{
  int node=(blockIdx.x*blockDim.x+threadIdx.x)>>5;
  int lane=threadIdx.x&31;
  if(node>=NN) return;
  const int h=lane>>3;
  const int beg=g_rowptr[node], end=g_rowptr[node+1];
  const float edv=((const float*)g_ed)[node*4+h];

  float4 acc=make_float4(0.f,0.f,0.f,0.f);
  float den=0.f;
  int j=beg;
  for(; j+1<end; j+=2){
    int s0=g_csrc[j], s1=g_csrc[j+1];
    float e0=((const float*)g_es)[s0*4+h];
    float e1=((const float*)g_es)[s1*4+h];
    float4 v0=*(const float4*)&g_hW[s0*HID+lane*4];
    float4 v1=*(const float4*)&g_hW[s1*HID+lane*4];
    float w0=__expf(lrelu(e0+edv));
    float w1=__expf(lrelu(e1+edv));
    acc.x+=w0*v0.x+w1*v1.x; acc.y+=w0*v0.y+w1*v1.y;
    acc.z+=w0*v0.z+w1*v1.z; acc.w+=w0*v0.w+w1*v1.w;
    den+=w0+w1;
  }
  if(j<end){
    int s=g_csrc[j];
    float w=__expf(lrelu(((const float*)g_es)[s*4+h]+edv));
    float4 v=*(const float4*)&g_hW[s*HID+lane*4];
    acc.x+=w*v.x; acc.y+=w*v.y; acc.z+=w*v.z; acc.w+=w*v.w;
    den+=w;
  }
  float inv=1.f/den;
  float4 v;
  v.x=acc.x*inv; v.y=acc.y*inv; v.z=acc.z*inv; v.w=acc.w*inv;

  if(FUSE_LN){
    float4 b4=*(const float4*)&bg[lane*4];
    v.x+=b4.x; v.y+=b4.y; v.z+=b4.z; v.w+=b4.w;
    float s=v.x+v.y+v.z+v.w;
    float q=v.x*v.x+v.y*v.y+v.z*v.z+v.w*v.w;
    #pragma unroll
    for(int o=16;o;o>>=1){
      s+=__shfl_xor_sync(0xffffffffu,s,o);
      q+=__shfl_xor_sync(0xffffffffu,q,o);
    }
    float mu=s*(1.f/HID);
    float rs=rsqrtf(q*(1.f/HID)-mu*mu+EPS);
    float4 gg=*(const float4*)&gam[lane*4];
    float4 b2=*(const float4*)&bet[lane*4];
    v.x=gelu_f((v.x-mu)*rs*gg.x+b2.x);
    v.y=gelu_f((v.y-mu)*rs*gg.y+b2.y);
    v.z=gelu_f((v.z-mu)*rs*gg.z+b2.z);
    v.w=gelu_f((v.w-mu)*rs*gg.w+b2.w);
    *(float4*)&g_h[node*HID+lane*4]=v;
  }else{
    *(float4*)&g_agg[node*HID+lane*4]=v;
  }
}

// ---------------- final: out = (agg + bg2) @ w_out + b_out -----------------
__global__ void __launch_bounds__(128) k_out(
    const float* __restrict__ bg, const float* __restrict__ w,
    const float* __restrict__ bo, float* __restrict__ out)
{
  __shared__ float ws[HID*OUTD];  // 32 KB
  __shared__ float hs[32*HID];    // 16 KB
  const int t=threadIdx.x;
  const int row0=blockIdx.x*32;
  const int nrows=min(32, NN-row0);

  for(int i=t;i<HID*OUTD;i+=128) ws[i]=w[i];
  for(int i=t;i<32*HID;i+=128){
    int r=i>>7, c=i&127;
    hs[i]=(r<nrows)? g_agg[row0*HID+i]+bg[c] : 0.f;
  }
  __syncthreads();

  const int cg=t&15, rg=t>>4;
  float acc[4][4];
  #pragma unroll
  for(int r=0;r<4;r++){acc[r][0]=0;acc[r][1]=0;acc[r][2]=0;acc[r][3]=0;}

  for(int k=0;k<HID;k++){
    float4 wv=*(float4*)&ws[k*OUTD+4*cg];
    #pragma unroll
    for(int r=0;r<4;r++){
      float hv=hs[(rg*4+r)*HID+k];
      acc[r][0]+=hv*wv.x; acc[r][1]+=hv*wv.y; acc[r][2]+=hv*wv.z; acc[r][3]+=hv*wv.w;
    }
  }
  float4 b4=*(const float4*)&bo[4*cg];
  #pragma unroll
  for(int r=0;r<4;r++){
    int row=row0+rg*4+r;
    if(row<NN)
      *(float4*)&out[row*OUTD+4*cg]=
        make_float4(acc[r][0]+b4.x,acc[r][1]+b4.y,acc[r][2]+b4.z,acc[r][3]+b4.w);
  }
}

// ---------------- launch ----------------------------------------------------
extern "C" void kernel_launch(void* const* d_in, const int* in_sizes, int n_in,
                              void* d_out, int out_size)
{
  const float* x    =(const float*)d_in[0];
  const int*   ei   =(const int*)d_in[1];
  const float* w_in =(const float*)d_in[2];
  const float* b_in =(const float*)d_in[3];
  const float* g1   =(const float*)d_in[4];
  const float* be1  =(const float*)d_in[5];
  const float* W1   =(const float*)d_in[6];
  const float* as1  =(const float*)d_in[7];
  const float* ad1  =(const float*)d_in[8];
  const float* bg1  =(const float*)d_in[9];
  const float* g2   =(const float*)d_in[10];
  const float* be2  =(const float*)d_in[11];
  const float* W2   =(const float*)d_in[12];
  const float* as2  =(const float*)d_in[13];
  const float* ad2  =(const float*)d_in[14];
  const float* bg2  =(const float*)d_in[15];
  const float* w_out=(const float*)d_in[16];
  const float* b_out=(const float*)d_in[17];
  float* out=(float*)d_out;

  const size_t shw=(HID*HID+32*HID+32*HID)*sizeof(float); // 96 KB
  cudaFuncSetAttribute(k_hw, cudaFuncAttributeMaxDynamicSharedMemorySize,(int)shw);

  const int gHW  =(NN+31)/32;
  const int gE   =(ETOT+255)/256;
  const int gN   =(NN+255)/256;
  const int gAGG =(NN*32+255)/256;   // warp per node

  // dense stage 1 + CSR build (CSR independent of features)
  k_in<<<NN/16,128>>>(x,w_in,b_in,g1,be1);
  k_zero_cnt<<<gN,256>>>();
  k_hist<<<gE,256>>>(ei);
  k_scan1<<<SCAN_B,SCAN_T>>>();
  k_scan2<<<1,SCAN_B>>>();
  k_scan3<<<SCAN_B,SCAN_T>>>();
  k_scatter<<<gE,256>>>(ei);

  // ---- GAT layer 1 (fused agg + LN + gelu)
  k_hw<<<gHW,128,shw>>>(W1,as1,ad1);
  k_agg<true><<<gAGG,256>>>(bg1,g2,be2);

  // ---- GAT layer 2
  k_hw<<<gHW,128,shw>>>(W2,as2,ad2);
  k_agg<false><<<gAGG,256>>>(nullptr,nullptr,nullptr);

  k_out<<<gHW,128>>>(bg2,w_out,b_out,out);
}

// round 11
// speedup vs baseline: 2.3989x; 1.2586x over previous
#include <cuda_runtime.h>
#include <math.h>

#define NN   50000
#define EE   1600000
#define ETOT (EE+NN)
#define IND  64
#define HID  128
#define NH   4
#define HD   32
#define OUTD 64
#define EPS  1e-5f

#define SCAN_B 128   // phase-1 blocks
#define SCAN_T 256   // phase-1 threads/block (each thread: 2 counts)

// ---------------- scratch (device globals; no allocation allowed) ----------
__device__ __align__(16) float    g_h  [NN*HID];   // activations between stages
__device__ __align__(16) float    g_hW [NN*HID];   // h @ W per GAT layer
__device__ __align__(16) float    g_agg[NN*HID];   // normalized aggregation (layer2)
__device__ __align__(16) float4   g_es [NN];       // per-node per-head src score
__device__ __align__(16) float4   g_ed [NN];       // per-node per-head dst score
__device__ int g_cnt   [NN];                       // CSR: per-dst degree
__device__ int g_rowptr[NN+1];                     // CSR: row pointers
__device__ int g_pos   [NN];                       // CSR: scatter cursors
__device__ int g_csrc  [ETOT];                     // CSR: src id per slot
__device__ int g_tpre  [SCAN_B*SCAN_T];            // scan: per-thread prefix
__device__ int g_bsum  [SCAN_B];                   // scan: block totals
__device__ int g_bbase [SCAN_B];                   // scan: block bases

// ---------------- helpers --------------------------------------------------
__device__ __forceinline__ float gelu_f(float x){
  return 0.5f*x*(1.f+tanhf(0.7978845608028654f*(x+0.044715f*x*x*x)));
}
__device__ __forceinline__ float lrelu(float x){ return x>0.f ? x : 0.2f*x; }
__device__ __forceinline__ int clampN(int v){
  return v<0?0:(v>=NN?NN-1:v);
}

// ---------------- stage 1: h = gelu(LN(x @ w_in + b_in)) -------------------
__global__ void __launch_bounds__(128) k_in(
    const float* __restrict__ x, const float* __restrict__ w,
    const float* __restrict__ b, const float* __restrict__ gam,
    const float* __restrict__ bet)
{
  __shared__ float ws[IND*HID];   // 32 KB
  __shared__ float xs[16*IND];    //  4 KB
  __shared__ float hb[16*HID];    //  8 KB
  const int t = threadIdx.x;
  const int row0 = blockIdx.x*16;   // 50000/16 = 3125 exact

  for(int i=t;i<IND*HID;i+=128) ws[i]=w[i];
  for(int i=t;i<16*IND;i+=128)  xs[i]=x[row0*IND+i];
  __syncthreads();

  const int cg=t&31, rg=t>>5;
  float4 bb=*(const float4*)&b[4*cg];
  float acc[4][4];
  #pragma unroll
  for(int r=0;r<4;r++){acc[r][0]=bb.x;acc[r][1]=bb.y;acc[r][2]=bb.z;acc[r][3]=bb.w;}

  for(int k=0;k<IND;k++){
    float4 wv=*(float4*)&ws[k*HID+4*cg];
    #pragma unroll
    for(int r=0;r<4;r++){
      float hv=xs[(rg*4+r)*IND+k];
      acc[r][0]+=hv*wv.x; acc[r][1]+=hv*wv.y; acc[r][2]+=hv*wv.z; acc[r][3]+=hv*wv.w;
    }
  }
  #pragma unroll
  for(int r=0;r<4;r++)
    *(float4*)&hb[(rg*4+r)*HID+4*cg]=make_float4(acc[r][0],acc[r][1],acc[r][2],acc[r][3]);
  __syncthreads();

  const int lane=t&31, wid=t>>5;
  float4 gg=*(const float4*)&gam[lane*4];
  float4 b2=*(const float4*)&bet[lane*4];
  for(int r=wid;r<16;r+=4){
    float4 v=*(float4*)&hb[r*HID+lane*4];
    float s=v.x+v.y+v.z+v.w;
    float q=v.x*v.x+v.y*v.y+v.z*v.z+v.w*v.w;
    #pragma unroll
    for(int o=16;o;o>>=1){
      s+=__shfl_xor_sync(0xffffffffu,s,o);
      q+=__shfl_xor_sync(0xffffffffu,q,o);
    }
    float mu=s*(1.f/HID);
    float rs=rsqrtf(q*(1.f/HID)-mu*mu+EPS);
    v.x=gelu_f((v.x-mu)*rs*gg.x+b2.x);
    v.y=gelu_f((v.y-mu)*rs*gg.y+b2.y);
    v.z=gelu_f((v.z-mu)*rs*gg.z+b2.z);
    v.w=gelu_f((v.w-mu)*rs*gg.w+b2.w);
    *(float4*)&g_h[(row0+r)*HID+lane*4]=v;
  }
}

// ---------------- stage 2: hW = h @ W ; e_src/e_dst ------------------------
// 256 threads, 64 rows/block, W streamed in two 64-row k-chunks.
// smem: Wc 32KB + hs 32KB + hwb 32KB = 96KB -> 2 blocks/SM (512 thr/SM).
__global__ void __launch_bounds__(256) k_hw(
    const float* __restrict__ W, const float* __restrict__ asrc,
    const float* __restrict__ adst)
{
  extern __shared__ float sm[];
  float* Wc  = sm;                 // 64x128 chunk of W (32 KB)
  float* hs  = sm + 64*HID;        // 64x128 inputs   (32 KB)
  float* hwb = hs + 64*HID;        // 64x128 outputs  (32 KB)
  const int t = threadIdx.x;
  const int row0 = blockIdx.x*64;
  const int nrows = min(64, NN-row0);

  for(int i=t;i<nrows*HID;i+=256) hs[i]=g_h[row0*HID+i];
  for(int i=nrows*HID+t;i<64*HID;i+=256) hs[i]=0.f;

  const int cg=t&31, rg=t>>5;      // cols 4*cg.., rows rg*8..rg*8+7
  float acc[8][4];
  #pragma unroll
  for(int r=0;r<8;r++){acc[r][0]=0;acc[r][1]=0;acc[r][2]=0;acc[r][3]=0;}

  for(int kc=0;kc<2;kc++){
    __syncthreads();
    for(int i=t;i<64*HID;i+=256) Wc[i]=W[kc*64*HID+i];
    __syncthreads();
    #pragma unroll 4
    for(int k=0;k<64;k++){
      float4 wv=*(float4*)&Wc[k*HID+4*cg];
      #pragma unroll
      for(int r=0;r<8;r++){
        float hv=hs[(rg*8+r)*HID+kc*64+k];
        acc[r][0]+=hv*wv.x; acc[r][1]+=hv*wv.y; acc[r][2]+=hv*wv.z; acc[r][3]+=hv*wv.w;
      }
    }
  }
  __syncthreads();
  #pragma unroll
  for(int r=0;r<8;r++)
    *(float4*)&hwb[(rg*8+r)*HID+4*cg]=make_float4(acc[r][0],acc[r][1],acc[r][2],acc[r][3]);
  __syncthreads();

  for(int i=t;i<nrows*HID;i+=256) g_hW[row0*HID+i]=hwb[i];

  // attention scores: warp per row (8 warps cycle over 64 rows)
  const int lane=t&31, wid=t>>5;
  for(int r=wid;r<nrows;r+=8){
    float ps[NH], pd[NH];
    #pragma unroll
    for(int h=0;h<NH;h++){
      float v=hwb[r*HID+h*HD+lane];
      ps[h]=v*asrc[h*HD+lane];
      pd[h]=v*adst[h*HD+lane];
    }
    #pragma unroll
    for(int o=16;o;o>>=1){
      #pragma unroll
      for(int h=0;h<NH;h++){
        ps[h]+=__shfl_xor_sync(0xffffffffu,ps[h],o);
        pd[h]+=__shfl_xor_sync(0xffffffffu,pd[h],o);
      }
    }
    if(lane==0){
      g_es[row0+r]=make_float4(ps[0],ps[1],ps[2],ps[3]);
      g_ed[row0+r]=make_float4(pd[0],pd[1],pd[2],pd[3]);
    }
  }
}

// ---------------- CSR build (once; reused by both layers) ------------------
__global__ void k_zero_cnt(){
  int i=blockIdx.x*blockDim.x+threadIdx.x;
  if(i<NN) g_cnt[i]=0;
}
__global__ void k_hist(const int* __restrict__ ei){
  int i=blockIdx.x*blockDim.x+threadIdx.x;
  if(i>=ETOT) return;
  int d = (i<EE)? clampN(ei[EE+i]) : i-EE;
  atomicAdd(&g_cnt[d],1);
}
// 3-phase device-wide exclusive scan of g_cnt -> g_rowptr/g_pos
__global__ void __launch_bounds__(SCAN_T) k_scan1(){
  __shared__ int sh[SCAN_T];
  const int t=threadIdx.x, b=blockIdx.x;
  const int g=b*SCAN_T+t;
  const int i0=g*2;
  int c0=(i0<NN)? g_cnt[i0]:0;
  int c1=(i0+1<NN)? g_cnt[i0+1]:0;
  sh[t]=c0+c1; __syncthreads();
  for(int off=1;off<SCAN_T;off<<=1){
    int v=(t>=off)? sh[t-off]:0; __syncthreads();
    sh[t]+=v; __syncthreads();
  }
  g_tpre[g]=(t==0)?0:sh[t-1];
  if(t==SCAN_T-1) g_bsum[b]=sh[SCAN_T-1];
}
__global__ void __launch_bounds__(SCAN_B) k_scan2(){
  __shared__ int sh[SCAN_B];
  const int t=threadIdx.x;
  sh[t]=g_bsum[t]; __syncthreads();
  for(int off=1;off<SCAN_B;off<<=1){
    int v=(t>=off)? sh[t-off]:0; __syncthreads();
    sh[t]+=v; __syncthreads();
  }
  g_bbase[t]=(t==0)?0:sh[t-1];
}
__global__ void __launch_bounds__(SCAN_T) k_scan3(){
  const int t=threadIdx.x, b=blockIdx.x;
  const int g=b*SCAN_T+t;
  const int i0=g*2;
  int base=g_bbase[b]+g_tpre[g];
  if(i0<NN){
    g_rowptr[i0]=base; g_pos[i0]=base;
    int nb=base+g_cnt[i0];
    if(i0+1<NN){ g_rowptr[i0+1]=nb; g_pos[i0+1]=nb; }
  }
  if(g==0) g_rowptr[NN]=ETOT;
}
__global__ void k_scatter(const int* __restrict__ ei){
  int i=blockIdx.x*blockDim.x+threadIdx.x;
  if(i>=ETOT) return;
  int s,d;
  if(i<EE){ s=clampN(ei[i]); d=clampN(ei[EE+i]); } else { s=d=i-EE; }
  int p=atomicAdd(&g_pos[d],1);
  g_csrc[p]=s;
}

// ---------------- fused aggregation: warp per dst node ---------------------
// acc = sum_e exp(lrelu(es[s]+ed[d])) * hW[s]; den = sum_e w; all in regs.
// 4-way unrolled gather loop for MLP. FUSE_LN: +bias+LN+gelu -> g_h.
template<bool FUSE_LN>
__global__ void __launch_bounds__(256) k_agg(
    const float* __restrict__ bg, const float* __restrict__ gam,
    const float* __restrict__ bet)
{
  int node=(blockIdx.x*blockDim.x+threadIdx.x)>>5;
  int lane=threadIdx.x&31;
  if(node>=NN) return;
  const int h=lane>>3;
  const int beg=g_rowptr[node], end=g_rowptr[node+1];
  const float edv=((const float*)g_ed)[node*4+h];

  float4 acc=make_float4(0.f,0.f,0.f,0.f);
  float den=0.f;
  int j=beg;
  for(; j+3<end; j+=4){
    int s0=g_csrc[j],   s1=g_csrc[j+1];
    int s2=g_csrc[j+2], s3=g_csrc[j+3];
    float e0=((const float*)g_es)[s0*4+h];
    float e1=((const float*)g_es)[s1*4+h];
    float e2=((const float*)g_es)[s2*4+h];
    float e3=((const float*)g_es)[s3*4+h];
    float4 v0=*(const float4*)&g_hW[s0*HID+lane*4];
    float4 v1=*(const float4*)&g_hW[s1*HID+lane*4];
    float4 v2=*(const float4*)&g_hW[s2*HID+lane*4];
    float4 v3=*(const float4*)&g_hW[s3*HID+lane*4];
    float w0=__expf(lrelu(e0+edv));
    float w1=__expf(lrelu(e1+edv));
    float w2=__expf(lrelu(e2+edv));
    float w3=__expf(lrelu(e3+edv));
    acc.x+=w0*v0.x+w1*v1.x+w2*v2.x+w3*v3.x;
    acc.y+=w0*v0.y+w1*v1.y+w2*v2.y+w3*v3.y;
    acc.z+=w0*v0.z+w1*v1.z+w2*v2.z+w3*v3.z;
    acc.w+=w0*v0.w+w1*v1.w+w2*v2.w+w3*v3.w;
    den+=(w0+w1)+(w2+w3);
  }
  for(; j<end; j++){
    int s=g_csrc[j];
    float w=__expf(lrelu(((const float*)g_es)[s*4+h]+edv));
    float4 v=*(const float4*)&g_hW[s*HID+lane*4];
    acc.x+=w*v.x; acc.y+=w*v.y; acc.z+=w*v.z; acc.w+=w*v.w;
    den+=w;
  }
  float inv=1.f/den;
  float4 v;
  v.x=acc.x*inv; v.y=acc.y*inv; v.z=acc.z*inv; v.w=acc.w*inv;

  if(FUSE_LN){
    float4 b4=*(const float4*)&bg[lane*4];
    v.x+=b4.x; v.y+=b4.y; v.z+=b4.z; v.w+=b4.w;
    float s=v.x+v.y+v.z+v.w;
    float q=v.x*v.x+v.y*v.y+v.z*v.z+v.w*v.w;
    #pragma unroll
    for(int o=16;o;o>>=1){
      s+=__shfl_xor_sync(0xffffffffu,s,o);
      q+=__shfl_xor_sync(0xffffffffu,q,o);
    }
    float mu=s*(1.f/HID);
    float rs=rsqrtf(q*(1.f/HID)-mu*mu+EPS);
    float4 gg=*(const float4*)&gam[lane*4];
    float4 b2=*(const float4*)&bet[lane*4];
    v.x=gelu_f((v.x-mu)*rs*gg.x+b2.x);
    v.y=gelu_f((v.y-mu)*rs*gg.y+b2.y);
    v.z=gelu_f((v.z-mu)*rs*gg.z+b2.z);
    v.w=gelu_f((v.w-mu)*rs*gg.w+b2.w);
    *(float4*)&g_h[node*HID+lane*4]=v;
  }else{
    *(float4*)&g_agg[node*HID+lane*4]=v;
  }
}

// ---------------- final: out = (agg + bg2) @ w_out + b_out -----------------
__global__ void __launch_bounds__(128) k_out(
    const float* __restrict__ bg, const float* __restrict__ w,
    const float* __restrict__ bo, float* __restrict__ out)
{
  __shared__ float ws[HID*OUTD];  // 32 KB
  __shared__ float hs[32*HID];    // 16 KB
  const int t=threadIdx.x;
  const int row0=blockIdx.x*32;
  const int nrows=min(32, NN-row0);

  for(int i=t;i<HID*OUTD;i+=128) ws[i]=w[i];
  for(int i=t;i<32*HID;i+=128){
    int r=i>>7, c=i&127;
    hs[i]=(r<nrows)? g_agg[row0*HID+i]+bg[c] : 0.f;
  }
  __syncthreads();

  const int cg=t&15, rg=t>>4;
  float acc[4][4];
  #pragma unroll
  for(int r=0;r<4;r++){acc[r][0]=0;acc[r][1]=0;acc[r][2]=0;acc[r][3]=0;}

  for(int k=0;k<HID;k++){
    float4 wv=*(float4*)&ws[k*OUTD+4*cg];
    #pragma unroll
    for(int r=0;r<4;r++){
      float hv=hs[(rg*4+r)*HID+k];
      acc[r][0]+=hv*wv.x; acc[r][1]+=hv*wv.y; acc[r][2]+=hv*wv.z; acc[r][3]+=hv*wv.w;
    }
  }
  float4 b4=*(const float4*)&bo[4*cg];
  #pragma unroll
  for(int r=0;r<4;r++){
    int row=row0+rg*4+r;
    if(row<NN)
      *(float4*)&out[row*OUTD+4*cg]=
        make_float4(acc[r][0]+b4.x,acc[r][1]+b4.y,acc[r][2]+b4.z,acc[r][3]+b4.w);
  }
}

// ---------------- launch ----------------------------------------------------
extern "C" void kernel_launch(void* const* d_in, const int* in_sizes, int n_in,
                              void* d_out, int out_size)
{
  const float* x    =(const float*)d_in[0];
  const int*   ei   =(const int*)d_in[1];
  const float* w_in =(const float*)d_in[2];
  const float* b_in =(const float*)d_in[3];
  const float* g1   =(const float*)d_in[4];
  const float* be1  =(const float*)d_in[5];
  const float* W1   =(const float*)d_in[6];
  const float* as1  =(const float*)d_in[7];
  const float* ad1  =(const float*)d_in[8];
  const float* bg1  =(const float*)d_in[9];
  const float* g2   =(const float*)d_in[10];
  const float* be2  =(const float*)d_in[11];
  const float* W2   =(const float*)d_in[12];
  const float* as2  =(const float*)d_in[13];
  const float* ad2  =(const float*)d_in[14];
  const float* bg2  =(const float*)d_in[15];
  const float* w_out=(const float*)d_in[16];
  const float* b_out=(const float*)d_in[17];
  float* out=(float*)d_out;

  const size_t shw=(64*HID*3)*sizeof(float); // 96 KB
  cudaFuncSetAttribute(k_hw, cudaFuncAttributeMaxDynamicSharedMemorySize,(int)shw);

  const int gHW  =(NN+63)/64;
  const int gO   =(NN+31)/32;
  const int gE   =(ETOT+255)/256;
  const int gN   =(NN+255)/256;
  const int gAGG =(NN*32+255)/256;   // warp per node

  // dense stage 1 + CSR build (CSR independent of features)
  k_in<<<NN/16,128>>>(x,w_in,b_in,g1,be1);
  k_zero_cnt<<<gN,256>>>();
  k_hist<<<gE,256>>>(ei);
  k_scan1<<<SCAN_B,SCAN_T>>>();
  k_scan2<<<1,SCAN_B>>>();
  k_scan3<<<SCAN_B,SCAN_T>>>();
  k_scatter<<<gE,256>>>(ei);

  // ---- GAT layer 1 (fused agg + LN + gelu)
  k_hw<<<gHW,256,shw>>>(W1,as1,ad1);
  k_agg<true><<<gAGG,256>>>(bg1,g2,be2);

  // ---- GAT layer 2
  k_hw<<<gHW,256,shw>>>(W2,as2,ad2);
  k_agg<false><<<gAGG,256>>>(nullptr,nullptr,nullptr);

  k_out<<<gO,128>>>(bg2,w_out,b_out,out);
}